// round 10
// baseline (speedup 1.0000x reference)
#include <cuda_runtime.h>
#include <cuda_bf16.h>

#define N_SAMPLE 12
#define D_FEAT 64
#define NODES_PER_WARP 4
#define PIPE 6   // gathers kept in flight per lane

typedef unsigned long long u64;

__device__ __forceinline__ void gather_v4b64(const float* __restrict__ fp,
                                             u64* r) {
    asm volatile("ld.global.nc.L2::evict_last.v4.b64 "
                 "{%0,%1,%2,%3}, [%4];"
                 : "=l"(r[0]), "=l"(r[1]), "=l"(r[2]), "=l"(r[3])
                 : "l"(fp));
}

__device__ __forceinline__ u64 addx2(u64 a, u64 b) {
    u64 r;
    asm("add.rn.f32x2 %0, %1, %2;" : "=l"(r) : "l"(a), "l"(b));
    return r;
}

template <bool GUARDED>
__global__ void __launch_bounds__(256, 4)
mean_agg_kernel(const float* __restrict__ feature,
                const int* __restrict__ neighbor_idx,
                float* __restrict__ out,
                int n_nodes) {
    int gwarp = (int)((blockIdx.x * (unsigned)blockDim.x + threadIdx.x) >> 5);
    int lane  = threadIdx.x & 31;
    int g     = lane >> 3;   // group 0..3 -> node within warp
    int lg    = lane & 7;    // lane in group: owns 8 floats (32 B) of the row

    int node = gwarp * NODES_PER_WARP + g;
    bool active = true;
    if (GUARDED) {
        active = node < n_nodes;
        if (!active) node = 0;   // clamp so inactive lanes load safely
    }

    // 12 indices per group: lanes 0..7 hold samples 0..7 (idx_a),
    // lanes 0..3 additionally hold samples 8..11 (idx_b).
    const int* ibase = neighbor_idx + (long long)node * N_SAMPLE;
    int idx_a = ibase[lg];
    int idx_b = (lg < 4) ? ibase[8 + lg] : 0;

    const float* fbase = feature + (long long)lg * 8;

    // Software pipeline, copy-free: buf[s] live from issue to consume;
    // full unroll lets the register allocator rename (peak ~PIPE+1 buffers).
    u64 buf[N_SAMPLE][4];

    // Prologue: issue samples 0..PIPE-1.
#pragma unroll
    for (int s = 0; s < PIPE; s++) {
        int id = __shfl_sync(0xffffffffu, idx_a, g * 8 + s);
        gather_v4b64(fbase + (long long)id * D_FEAT, buf[s]);
    }

    u64 acc0 = 0, acc1 = 0, acc2 = 0, acc3 = 0;  // 0.0f|0.0f packed

    // Steady state: issue sample s+PIPE, then consume sample s.
#pragma unroll
    for (int s = 0; s < N_SAMPLE; s++) {
        int s2 = s + PIPE;
        if (s2 < N_SAMPLE) {
            int src = g * 8 + (s2 < 8 ? s2 : s2 - 8);
            int id  = __shfl_sync(0xffffffffu, (s2 < 8) ? idx_a : idx_b, src);
            gather_v4b64(fbase + (long long)id * D_FEAT, buf[s2]);
        }
        acc0 = addx2(acc0, buf[s][0]);
        acc1 = addx2(acc1, buf[s][1]);
        acc2 = addx2(acc2, buf[s][2]);
        acc3 = addx2(acc3, buf[s][3]);
    }

    if (!GUARDED || active) {
        const float inv = 1.0f / (float)N_SAMPLE;
        unsigned invb = __float_as_uint(inv);
        u64 inv2 = ((u64)invb << 32) | invb;
        u64 w0, w1, w2, w3;
        asm("mul.rn.f32x2 %0, %1, %2;" : "=l"(w0) : "l"(acc0), "l"(inv2));
        asm("mul.rn.f32x2 %0, %1, %2;" : "=l"(w1) : "l"(acc1), "l"(inv2));
        asm("mul.rn.f32x2 %0, %1, %2;" : "=l"(w2) : "l"(acc2), "l"(inv2));
        asm("mul.rn.f32x2 %0, %1, %2;" : "=l"(w3) : "l"(acc3), "l"(inv2));
        float* op = out + (long long)node * D_FEAT + lg * 8;
        // Streaming write-once output: don't evict feature lines.
        asm volatile("st.global.L2::evict_first.v4.b64 [%0], {%1,%2,%3,%4};"
                     :: "l"(op), "l"(w0), "l"(w1), "l"(w2), "l"(w3)
                     : "memory");
    }
}

extern "C" void kernel_launch(void* const* d_in, const int* in_sizes, int n_in,
                              void* d_out, int out_size) {
    const float* feature      = (const float*)d_in[0];
    const int*   neighbor_idx = (const int*)d_in[1];
    float*       out          = (float*)d_out;

    int n_nodes = in_sizes[1] / N_SAMPLE;

    const int nodes_per_block = (256 / 32) * NODES_PER_WARP;  // 32
    int blocks = (n_nodes + nodes_per_block - 1) / nodes_per_block;

    if (n_nodes % nodes_per_block == 0) {
        // Exact cover (the benchmark shape: 100000 = 3125 * 32) — no guards.
        mean_agg_kernel<false><<<blocks, 256>>>(feature, neighbor_idx, out, n_nodes);
    } else {
        mean_agg_kernel<true><<<blocks, 256>>>(feature, neighbor_idx, out, n_nodes);
    }
}

// round 11
// speedup vs baseline: 1.3099x; 1.3099x over previous
#include <cuda_runtime.h>
#include <cuda_bf16.h>

#define N_SAMPLE 12
#define D_FEAT 64
#define NODES_PER_WARP 4
#define HALF 6

__device__ __forceinline__ void gather_v8(const float* __restrict__ fp,
                                          unsigned* r) {
    asm volatile("ld.global.nc.L2::evict_last.v8.b32 "
                 "{%0,%1,%2,%3,%4,%5,%6,%7}, [%8];"
                 : "=r"(r[0]),"=r"(r[1]),"=r"(r[2]),"=r"(r[3]),
                   "=r"(r[4]),"=r"(r[5]),"=r"(r[6]),"=r"(r[7])
                 : "l"(fp));
}

template <bool GUARDED>
__global__ void __launch_bounds__(256, 4)
mean_agg_kernel(const float* __restrict__ feature,
                const int* __restrict__ neighbor_idx,
                float* __restrict__ out,
                int n_nodes) {
    int gwarp = (int)((blockIdx.x * (unsigned)blockDim.x + threadIdx.x) >> 5);
    int lane  = threadIdx.x & 31;
    int g     = lane >> 3;   // group 0..3 -> node within warp
    int lg    = lane & 7;    // lane in group: owns 8 floats (32 B) of the row

    int node = gwarp * NODES_PER_WARP + g;
    bool active = true;
    if (GUARDED) {
        active = node < n_nodes;
        if (!active) node = 0;   // clamp so inactive lanes load safely
    }

    // 12 indices per group: lanes 0..7 hold samples 0..7 (idx_a),
    // lanes 0..3 additionally hold samples 8..11 (idx_b).
    const int* ibase = neighbor_idx + (long long)node * N_SAMPLE;
    int idx_a = ibase[lg];
    int idx_b = (lg < 4) ? ibase[8 + lg] : 0;

    const float* fbase = feature + (long long)lg * 8;

    float acc[8];
#pragma unroll
    for (int k = 0; k < 8; k++) acc[k] = 0.f;

    // Software pipeline: keep ~6 v8 gathers (192 B/lane) in flight.
    unsigned buf[HALF][8];

    // Prologue: issue samples 0..5.
#pragma unroll
    for (int s = 0; s < HALF; s++) {
        int id = __shfl_sync(0xffffffffu, idx_a, g * 8 + s);
        gather_v8(fbase + (long long)id * D_FEAT, buf[s]);
    }

    // Steady state: for each consumed sample s, issue sample s+6 first.
#pragma unroll
    for (int s = 0; s < HALF; s++) {
        int s2 = s + HALF;  // 6..11
        int src = g * 8 + (s2 < 8 ? s2 : s2 - 8);
        int id  = __shfl_sync(0xffffffffu, (s2 < 8) ? idx_a : idx_b, src);
        unsigned nxt[8];
        gather_v8(fbase + (long long)id * D_FEAT, nxt);
#pragma unroll
        for (int k = 0; k < 8; k++) acc[k] += __uint_as_float(buf[s][k]);
#pragma unroll
        for (int k = 0; k < 8; k++) buf[s][k] = nxt[k];
    }

    // Epilogue: consume samples 6..11.
#pragma unroll
    for (int s = 0; s < HALF; s++) {
#pragma unroll
        for (int k = 0; k < 8; k++) acc[k] += __uint_as_float(buf[s][k]);
    }

    const float inv = 1.0f / (float)N_SAMPLE;
    if (!GUARDED || active) {
        float* op = out + (long long)node * D_FEAT + lg * 8;
        unsigned w[8];
#pragma unroll
        for (int k = 0; k < 8; k++) w[k] = __float_as_uint(acc[k] * inv);
        // Streaming write-once output: don't evict feature lines.
        asm volatile("st.global.L2::evict_first.v8.b32 [%0], "
                     "{%1,%2,%3,%4,%5,%6,%7,%8};"
                     :: "l"(op),
                        "r"(w[0]),"r"(w[1]),"r"(w[2]),"r"(w[3]),
                        "r"(w[4]),"r"(w[5]),"r"(w[6]),"r"(w[7])
                     : "memory");
    }
}

extern "C" void kernel_launch(void* const* d_in, const int* in_sizes, int n_in,
                              void* d_out, int out_size) {
    const float* feature      = (const float*)d_in[0];
    const int*   neighbor_idx = (const int*)d_in[1];
    float*       out          = (float*)d_out;

    int n_nodes = in_sizes[1] / N_SAMPLE;

    const int nodes_per_block = (256 / 32) * NODES_PER_WARP;  // 32
    int blocks = (n_nodes + nodes_per_block - 1) / nodes_per_block;

    if (n_nodes % nodes_per_block == 0) {
        // Exact cover (the benchmark shape: 100000 = 3125 * 32) — no guards.
        mean_agg_kernel<false><<<blocks, 256>>>(feature, neighbor_idx, out, n_nodes);
    } else {
        mean_agg_kernel<true><<<blocks, 256>>>(feature, neighbor_idx, out, n_nodes);
    }
}